// round 4
// baseline (speedup 1.0000x reference)
#include <cuda_runtime.h>
#include <cstdint>

#define B_   128
#define T_   512
#define E_   512
#define H_   1024
#define G3H_ 3072
#define NROW 65536   // B*T

#define NCTA 128     // CTAs in persistent recurrence
#define COLS 8       // h-columns per CTA
#define WROW 24      // 3 gates * COLS weight rows per CTA
#define WPAD 1028    // W smem row stride (words) -> conflict-free B reads
#define BK   32
#define ASTRIDE 36   // h-tile smem row stride (words), 32 + 4 pad
#define ASTAGE (128*ASTRIDE)
#define GXSTRIDE 24  // gx smem row stride (words), 16B-aligned rows
#define REC_WORDS (WROW*WPAD + 3*ASTAGE + 128*GXSTRIDE + 128*8 + 32)
#define REC_SMEM (REC_WORDS * 4)

// ---------------- device scratch ----------------
__device__ float g_x0 [(size_t)NROW * E_];
__device__ float g_y0 [(size_t)NROW * H_];
__device__ float g_gx0[(size_t)NROW * G3H_];
__device__ float g_gx1[(size_t)NROW * G3H_];
__device__ float g_wih0[G3H_ * E_];
__device__ float g_wih1[G3H_ * H_];
__device__ float g_h0[2][B_ * H_];
__device__ float g_h1[2][B_ * H_];
__device__ unsigned g_bar0;
__device__ unsigned g_bar1;

// ---------------- helpers ----------------
__device__ __forceinline__ float tf32r(float x) {
    uint32_t u;
    asm("cvt.rna.tf32.f32 %0, %1;" : "=r"(u) : "f"(x));
    return __uint_as_float(u);
}
__device__ __forceinline__ void cp16(void* s, const void* g) {
    uint32_t sa = (uint32_t)__cvta_generic_to_shared(s);
    asm volatile("cp.async.cg.shared.global [%0], [%1], 16;" :: "r"(sa), "l"(g));
}
__device__ __forceinline__ void cpcommit() { asm volatile("cp.async.commit_group;"); }
__device__ __forceinline__ void cpwait1()  { asm volatile("cp.async.wait_group 1;"); }

__device__ __forceinline__ void mma8(float c[4], const uint32_t a[4], const uint32_t b[2]) {
    asm volatile(
        "mma.sync.aligned.m16n8k8.row.col.f32.tf32.tf32.f32 "
        "{%0,%1,%2,%3}, {%4,%5,%6,%7}, {%8,%9}, {%0,%1,%2,%3};"
        : "+f"(c[0]), "+f"(c[1]), "+f"(c[2]), "+f"(c[3])
        : "r"(a[0]), "r"(a[1]), "r"(a[2]), "r"(a[3]), "r"(b[0]), "r"(b[1]));
}

__device__ __forceinline__ void grid_sync(unsigned* bar, unsigned target) {
    __syncthreads();
    if (threadIdx.x == 0) {
        asm volatile("red.release.gpu.global.add.u32 [%0], 1;" :: "l"(bar) : "memory");
        unsigned v;
        do {
            asm volatile("ld.acquire.gpu.global.u32 %0, [%1];" : "=r"(v) : "l"(bar) : "memory");
        } while (v < target);
    }
    __syncthreads();
}

// ---------------- fused setup: tf32-round wih weights, zero h, reset barriers ----------------
__global__ void k_setup(const float* __restrict__ wih0, const float* __restrict__ wih1) {
    int stride = gridDim.x * blockDim.x;
    for (int i = blockIdx.x * blockDim.x + threadIdx.x; i < G3H_ * H_; i += stride) {
        if (i < G3H_ * E_) g_wih0[i] = tf32r(wih0[i]);
        g_wih1[i] = tf32r(wih1[i]);
        if (i < 2 * B_ * H_) { (&g_h0[0][0])[i] = 0.f; (&g_h1[0][0])[i] = 0.f; }
        if (i == 0) { g_bar0 = 0; g_bar1 = 0; }
    }
}

__global__ void k_gather(const int* __restrict__ src, const float* __restrict__ emb,
                         float* __restrict__ x0) {
    int row = blockIdx.x;
    int v = src[row];
    const float* e = emb + (size_t)v * E_;
    float* o = x0 + (size_t)row * E_;
    for (int j = threadIdx.x; j < E_; j += blockDim.x) o[j] = tf32r(e[j]);
}

// ---------------- big input-projection GEMM: C[M,3072] = A[M,K]*W[3072,K]^T + bias ----------------
__device__ __forceinline__ void gemm_load(float (*As)[20], float (*Ws)[20],
                                          const float* Ab, const float* Wb,
                                          int K, int kt, int tid) {
    #pragma unroll
    for (int i = 0; i < 2; i++) {
        int id = tid + 256 * i;
        int r = id >> 2, s = id & 3;
        cp16(&As[r][s * 4], Ab + (size_t)r * K + kt * 16 + s * 4);
        cp16(&Ws[r][s * 4], Wb + (size_t)r * K + kt * 16 + s * 4);
    }
    cpcommit();
}

__global__ __launch_bounds__(256) void k_gemm(const float* __restrict__ A,
                                              const float* __restrict__ W,
                                              const float* __restrict__ bias,
                                              float* __restrict__ C, int K) {
    __shared__ float As[3][128][20];
    __shared__ float Ws[3][128][20];
    int tid = threadIdx.x;
    int lane = tid & 31, wid = tid >> 5;
    int g = lane >> 2, tg = lane & 3;
    int wM = wid & 1, wN = wid >> 1;
    const float* Ab = A + (size_t)blockIdx.y * 128 * K;
    const float* Wb = W + (size_t)blockIdx.x * 128 * K;

    float c[4][4][4];
    #pragma unroll
    for (int i = 0; i < 4; i++)
        #pragma unroll
        for (int j = 0; j < 4; j++)
            #pragma unroll
            for (int e = 0; e < 4; e++) c[i][j][e] = 0.f;

    int KIT = K >> 4;
    gemm_load(As[0], Ws[0], Ab, Wb, K, 0, tid);
    gemm_load(As[1], Ws[1], Ab, Wb, K, 1, tid);

    for (int kt = 0; kt < KIT; kt++) {
        cpwait1();
        __syncthreads();
        if (kt + 2 < KIT) gemm_load(As[(kt + 2) % 3], Ws[(kt + 2) % 3], Ab, Wb, K, kt + 2, tid);
        else cpcommit();
        int cur = kt % 3;
        #pragma unroll
        for (int ks = 0; ks < 2; ks++) {
            uint32_t a[4][4], b[4][2];
            #pragma unroll
            for (int mt = 0; mt < 4; mt++) {
                int r0 = wM * 64 + mt * 16 + g;
                a[mt][0] = __float_as_uint(As[cur][r0    ][ks * 8 + tg]);
                a[mt][1] = __float_as_uint(As[cur][r0 + 8][ks * 8 + tg]);
                a[mt][2] = __float_as_uint(As[cur][r0    ][ks * 8 + tg + 4]);
                a[mt][3] = __float_as_uint(As[cur][r0 + 8][ks * 8 + tg + 4]);
            }
            #pragma unroll
            for (int nt = 0; nt < 4; nt++) {
                int n0 = wN * 32 + nt * 8 + g;
                b[nt][0] = __float_as_uint(Ws[cur][n0][ks * 8 + tg]);
                b[nt][1] = __float_as_uint(Ws[cur][n0][ks * 8 + tg + 4]);
            }
            #pragma unroll
            for (int mt = 0; mt < 4; mt++)
                #pragma unroll
                for (int nt = 0; nt < 4; nt++) mma8(c[mt][nt], a[mt], b[nt]);
        }
        __syncthreads();
    }

    size_t row0 = (size_t)blockIdx.y * 128;
    int col0 = blockIdx.x * 128 + wN * 32;
    #pragma unroll
    for (int mt = 0; mt < 4; mt++)
        #pragma unroll
        for (int nt = 0; nt < 4; nt++)
            #pragma unroll
            for (int ep = 0; ep < 2; ep++) {
                size_t row = row0 + wM * 64 + mt * 16 + g + ep * 8;
                int col = col0 + nt * 8 + 2 * tg;
                float2 v;
                v.x = c[mt][nt][2 * ep]     + bias[col];
                v.y = c[mt][nt][2 * ep + 1] + bias[col + 1];
                *(float2*)&C[row * G3H_ + col] = v;
            }
}

// ---------------- persistent recurrence: weights SMEM-resident, 512 steps ----------------
__global__ __launch_bounds__(256) void k_rec_persist(
    const float* __restrict__ W,     // whh raw fp32 [3072][1024]
    const float* __restrict__ gx,    // [B][T][3H] fp32
    const float* __restrict__ bhh,   // [3H]
    float* __restrict__ hbuf,        // [2][B*H] ping-pong
    float* __restrict__ yout,        // [B][T][H] or nullptr
    float* __restrict__ outf,        // [B][H] final hidden (fp32)
    unsigned* __restrict__ bar) {
    extern __shared__ float smem[];
    float* Ws    = smem;                          // [WROW][WPAD]
    float* As    = Ws + WROW * WPAD;              // 3 stages [128][ASTRIDE]
    float* gxs   = As + 3 * ASTAGE;               // [128][GXSTRIDE]
    float* holds = gxs + 128 * GXSTRIDE;          // [128][8]
    float* bhs   = holds + 128 * 8;               // [24]

    int tid = threadIdx.x;
    int lane = tid & 31, wid = tid >> 5;          // wid = wM (0..7)
    int g = lane >> 2, tg = lane & 3;
    int nb = blockIdx.x * COLS;

    // resident weights: smem row j -> global row (j/8)*1024 + nb + (j%8)
    for (int i = tid; i < WROW * 1024; i += 256) {
        int j = i >> 10, k = i & 1023;
        int grow = (j >> 3) * H_ + nb + (j & 7);
        Ws[j * WPAD + k] = tf32r(W[(size_t)grow * H_ + k]);
    }
    if (tid < 24) bhs[tid] = bhh[(tid >> 3) * H_ + nb + (tid & 7)];
    __syncthreads();

    for (int t = 0; t < T_; t++) {
        const float* hin = hbuf + (size_t)(t & 1) * (B_ * H_);
        float* hout = hbuf + (size_t)((t + 1) & 1) * (B_ * H_);

        float c[3][4];
        #pragma unroll
        for (int j = 0; j < 3; j++)
            #pragma unroll
            for (int e = 0; e < 4; e++) c[j][e] = 0.f;

        // ---- group 0: stage 0 of h-tile + gx tile + hold block ----
        {
            float* dst = As;
            #pragma unroll
            for (int i = 0; i < 4; i++) {
                int idx = tid + 256 * i;
                int r = idx >> 3, sc = idx & 7;
                cp16(dst + r * ASTRIDE + sc * 4, hin + (size_t)r * H_ + sc * 4);
            }
            // gx tile: per row 3 gates x 8 floats
            #pragma unroll
            for (int i = 0; i < 3; i++) {
                int idx = tid + 256 * i;
                int r = idx / 6, part = idx % 6;
                int gt = part >> 1, half = part & 1;
                cp16(gxs + r * GXSTRIDE + gt * 8 + half * 4,
                     gx + (size_t)r * (T_ * G3H_) + (size_t)t * G3H_ + gt * H_ + nb + half * 4);
            }
            // hold block: h_old for this CTA's 8 columns
            {
                int r = tid >> 1, half = tid & 1;
                cp16(holds + r * 8 + half * 4, hin + (size_t)r * H_ + nb + half * 4);
            }
            cpcommit();
        }
        // ---- group 1: stage 1 ----
        {
            float* dst = As + ASTAGE;
            #pragma unroll
            for (int i = 0; i < 4; i++) {
                int idx = tid + 256 * i;
                int r = idx >> 3, sc = idx & 7;
                cp16(dst + r * ASTRIDE + sc * 4, hin + (size_t)r * H_ + BK + sc * 4);
            }
            cpcommit();
        }

        for (int kt = 0; kt < 32; kt++) {           // K = 1024, BK = 32
            cpwait1();
            __syncthreads();
            if (kt + 2 < 32) {
                float* dst = As + ((kt + 2) % 3) * ASTAGE;
                #pragma unroll
                for (int i = 0; i < 4; i++) {
                    int idx = tid + 256 * i;
                    int r = idx >> 3, sc = idx & 7;
                    cp16(dst + r * ASTRIDE + sc * 4,
                         hin + (size_t)r * H_ + (kt + 2) * BK + sc * 4);
                }
            }
            cpcommit();

            const float* A = As + (kt % 3) * ASTAGE;
            #pragma unroll
            for (int ks = 0; ks < 4; ks++) {
                int ko = ks * 8;
                uint32_t a[4];
                int r0 = wid * 16 + g;
                a[0] = __float_as_uint(A[r0 * ASTRIDE + ko + tg]);
                a[1] = __float_as_uint(A[(r0 + 8) * ASTRIDE + ko + tg]);
                a[2] = __float_as_uint(A[r0 * ASTRIDE + ko + tg + 4]);
                a[3] = __float_as_uint(A[(r0 + 8) * ASTRIDE + ko + tg + 4]);
                #pragma unroll
                for (int gt = 0; gt < 3; gt++) {
                    uint32_t b[2];
                    int j = gt * COLS + g;
                    b[0] = __float_as_uint(Ws[j * WPAD + kt * BK + ko + tg]);
                    b[1] = __float_as_uint(Ws[j * WPAD + kt * BK + ko + tg + 4]);
                    mma8(c[gt], a, b);
                }
            }
        }

        // epilogue: fused GRU pointwise, all operands in SMEM
        #pragma unroll
        for (int ep = 0; ep < 2; ep++) {
            int row = wid * 16 + g + ep * 8;
            float2 hv;
            #pragma unroll
            for (int half = 0; half < 2; half++) {
                int e = 2 * ep + half;
                int lc = 2 * tg + half;
                float xr = gxs[row * GXSTRIDE + lc];
                float xz = gxs[row * GXSTRIDE + 8 + lc];
                float xn = gxs[row * GXSTRIDE + 16 + lc];
                float hr = c[0][e] + bhs[lc];
                float hz = c[1][e] + bhs[8 + lc];
                float hn = c[2][e] + bhs[16 + lc];
                float rr = 1.f / (1.f + expf(-(xr + hr)));
                float zz = 1.f / (1.f + expf(-(xz + hz)));
                float nn = tanhf(xn + rr * hn);
                float hold = holds[row * 8 + lc];
                float hnew = (1.f - zz) * nn + zz * hold;
                (half ? hv.y : hv.x) = hnew;
            }
            int col = nb + 2 * tg;
            float2 hq = { tf32r(hv.x), tf32r(hv.y) };
            *(float2*)&hout[(size_t)row * H_ + col] = hq;
            if (yout) *(float2*)&yout[(size_t)row * (T_ * H_) + (size_t)t * H_ + col] = hq;
            if (t == T_ - 1) *(float2*)&outf[(size_t)row * H_ + col] = hv;
        }

        if (t != T_ - 1) grid_sync(bar, (unsigned)(t + 1) * NCTA);
    }
}

// ---------------- launch ----------------
extern "C" void kernel_launch(void* const* d_in, const int* in_sizes, int n_in,
                              void* d_out, int out_size) {
    const int*   src  = (const int*)d_in[0];
    const float* emb  = (const float*)d_in[1];
    const float* wih0 = (const float*)d_in[2];
    const float* whh0 = (const float*)d_in[3];
    const float* bih0 = (const float*)d_in[4];
    const float* bhh0 = (const float*)d_in[5];
    const float* wih1 = (const float*)d_in[6];
    const float* whh1 = (const float*)d_in[7];
    const float* bih1 = (const float*)d_in[8];
    const float* bhh1 = (const float*)d_in[9];
    float* out = (float*)d_out;

    float *x0, *y0, *gx0, *gx1, *pwih0, *pwih1, *h0, *h1;
    unsigned *bar0, *bar1;
    cudaGetSymbolAddress((void**)&x0,    g_x0);
    cudaGetSymbolAddress((void**)&y0,    g_y0);
    cudaGetSymbolAddress((void**)&gx0,   g_gx0);
    cudaGetSymbolAddress((void**)&gx1,   g_gx1);
    cudaGetSymbolAddress((void**)&pwih0, g_wih0);
    cudaGetSymbolAddress((void**)&pwih1, g_wih1);
    cudaGetSymbolAddress((void**)&h0,    g_h0);
    cudaGetSymbolAddress((void**)&h1,    g_h1);
    cudaGetSymbolAddress((void**)&bar0,  g_bar0);
    cudaGetSymbolAddress((void**)&bar1,  g_bar1);

    cudaFuncSetAttribute(k_rec_persist, cudaFuncAttributeMaxDynamicSharedMemorySize, REC_SMEM);

    // launch order keeps k_rec_persist at my-launch-index 3 so ncu (-s 5) captures it
    k_setup<<<2048, 256>>>(wih0, wih1);                       // 0
    k_gather<<<NROW, 128>>>(src, emb, x0);                    // 1
    k_gemm<<<dim3(24, 512), 256>>>(x0, pwih0, bih0, gx0, E_); // 2
    k_rec_persist<<<NCTA, 256, REC_SMEM>>>(whh0, gx0, bhh0, h0, y0, out, bar0);      // 3
    k_gemm<<<dim3(24, 512), 256>>>(y0, pwih1, bih1, gx1, H_); // 4
    k_rec_persist<<<NCTA, 256, REC_SMEM>>>(whh1, gx1, bhh1, h1, nullptr, out + B_ * H_, bar1); // 5
}

// round 5
// speedup vs baseline: 1.7321x; 1.7321x over previous
#include <cuda_runtime.h>
#include <cstdint>

#define B_   128
#define T_   512
#define E_   512
#define H_   1024
#define G3H_ 3072
#define NROW 65536   // B*T

#define NCTA 128     // CTAs in persistent recurrence
#define COLS 8       // h-columns per CTA
#define BK   32      // k per stage
#define NSTG 4       // per-warp stages

// SMEM layout (words)
#define WP_WORDS   24576                 // packed weights [32kt][4ks][3gt][32lane][2]
#define ASTG_ROW   36                    // per-warp stage row stride (16 rows)
#define ASTG_WORDS (16*ASTG_ROW)         // 576 words per stage
#define AS_WORDS   (8*NSTG*ASTG_WORDS)   // 18432
#define GX_ROW     24
#define GX_WORDS   (8*16*GX_ROW)         // 3072
#define HOLD_WORDS (8*16*8)              // 1024
#define REC_WORDS  (WP_WORDS + AS_WORDS + GX_WORDS + HOLD_WORDS + 32)
#define REC_SMEM   (REC_WORDS * 4)

// ---------------- device scratch ----------------
__device__ float g_x0 [(size_t)NROW * E_];
__device__ float g_y0 [(size_t)NROW * H_];
__device__ float g_gx0[(size_t)NROW * G3H_];
__device__ float g_gx1[(size_t)NROW * G3H_];
__device__ float g_wih0[G3H_ * E_];
__device__ float g_wih1[G3H_ * H_];
__device__ float g_h0[2][B_ * H_];
__device__ float g_h1[2][B_ * H_];
__device__ unsigned g_flags0[NCTA * 32];   // 128B-padded per-CTA epoch flags
__device__ unsigned g_flags1[NCTA * 32];

// ---------------- helpers ----------------
__device__ __forceinline__ float tf32r(float x) {
    uint32_t u;
    asm("cvt.rna.tf32.f32 %0, %1;" : "=r"(u) : "f"(x));
    return __uint_as_float(u);
}
__device__ __forceinline__ void cp16(void* s, const void* g) {
    uint32_t sa = (uint32_t)__cvta_generic_to_shared(s);
    asm volatile("cp.async.cg.shared.global [%0], [%1], 16;" :: "r"(sa), "l"(g));
}
__device__ __forceinline__ void cpcommit() { asm volatile("cp.async.commit_group;"); }
__device__ __forceinline__ void cpwait2()  { asm volatile("cp.async.wait_group 2;"); }

__device__ __forceinline__ void mma8(float c[4], const uint32_t a[4], const uint32_t b[2]) {
    asm volatile(
        "mma.sync.aligned.m16n8k8.row.col.f32.tf32.tf32.f32 "
        "{%0,%1,%2,%3}, {%4,%5,%6,%7}, {%8,%9}, {%0,%1,%2,%3};"
        : "+f"(c[0]), "+f"(c[1]), "+f"(c[2]), "+f"(c[3])
        : "r"(a[0]), "r"(a[1]), "r"(a[2]), "r"(a[3]), "r"(b[0]), "r"(b[1]));
}

// distributed-flag grid barrier: write own flag (release), poll all (acquire)
__device__ __forceinline__ void flag_barrier(unsigned* flags, int bid, int wid, int lane,
                                             unsigned target) {
    __syncthreads();
    if (wid == 0) {
        if (lane == 0)
            asm volatile("st.release.gpu.global.u32 [%0], %1;"
                         :: "l"(flags + bid * 32), "r"(target) : "memory");
        unsigned ok;
        do {
            ok = 1u;
            #pragma unroll
            for (int i = 0; i < 4; i++) {
                unsigned v;
                asm volatile("ld.acquire.gpu.global.u32 %0, [%1];"
                             : "=r"(v) : "l"(flags + (lane + 32 * i) * 32) : "memory");
                ok &= (v >= target) ? 1u : 0u;
            }
        } while (!__all_sync(0xffffffffu, ok));
    }
    __syncthreads();
}

// ---------------- fused setup ----------------
__global__ void k_setup(const float* __restrict__ wih0, const float* __restrict__ wih1) {
    int stride = gridDim.x * blockDim.x;
    for (int i = blockIdx.x * blockDim.x + threadIdx.x; i < G3H_ * H_; i += stride) {
        if (i < G3H_ * E_) g_wih0[i] = tf32r(wih0[i]);
        g_wih1[i] = tf32r(wih1[i]);
        if (i < 2 * B_ * H_) { (&g_h0[0][0])[i] = 0.f; (&g_h1[0][0])[i] = 0.f; }
        if (i < NCTA * 32) { g_flags0[i] = 0u; g_flags1[i] = 0u; }
    }
}

__global__ void k_gather(const int* __restrict__ src, const float* __restrict__ emb,
                         float* __restrict__ x0) {
    int row = blockIdx.x;
    int v = src[row];
    const float* e = emb + (size_t)v * E_;
    float* o = x0 + (size_t)row * E_;
    for (int j = threadIdx.x; j < E_; j += blockDim.x) o[j] = tf32r(e[j]);
}

// ---------------- big input-projection GEMM: C[M,3072] = A[M,K]*W[3072,K]^T + bias ----------------
__device__ __forceinline__ void gemm_load(float (*As)[20], float (*Ws)[20],
                                          const float* Ab, const float* Wb,
                                          int K, int kt, int tid) {
    #pragma unroll
    for (int i = 0; i < 2; i++) {
        int id = tid + 256 * i;
        int r = id >> 2, s = id & 3;
        cp16(&As[r][s * 4], Ab + (size_t)r * K + kt * 16 + s * 4);
        cp16(&Ws[r][s * 4], Wb + (size_t)r * K + kt * 16 + s * 4);
    }
    cpcommit();
}

__global__ __launch_bounds__(256) void k_gemm(const float* __restrict__ A,
                                              const float* __restrict__ W,
                                              const float* __restrict__ bias,
                                              float* __restrict__ C, int K) {
    __shared__ float As[3][128][20];
    __shared__ float Ws[3][128][20];
    int tid = threadIdx.x;
    int lane = tid & 31, wid = tid >> 5;
    int g = lane >> 2, tg = lane & 3;
    int wM = wid & 1, wN = wid >> 1;
    const float* Ab = A + (size_t)blockIdx.y * 128 * K;
    const float* Wb = W + (size_t)blockIdx.x * 128 * K;

    float c[4][4][4];
    #pragma unroll
    for (int i = 0; i < 4; i++)
        #pragma unroll
        for (int j = 0; j < 4; j++)
            #pragma unroll
            for (int e = 0; e < 4; e++) c[i][j][e] = 0.f;

    int KIT = K >> 4;
    gemm_load(As[0], Ws[0], Ab, Wb, K, 0, tid);
    gemm_load(As[1], Ws[1], Ab, Wb, K, 1, tid);

    for (int kt = 0; kt < KIT; kt++) {
        asm volatile("cp.async.wait_group 1;");
        __syncthreads();
        if (kt + 2 < KIT) gemm_load(As[(kt + 2) % 3], Ws[(kt + 2) % 3], Ab, Wb, K, kt + 2, tid);
        else cpcommit();
        int cur = kt % 3;
        #pragma unroll
        for (int ks = 0; ks < 2; ks++) {
            uint32_t a[4][4], b[4][2];
            #pragma unroll
            for (int mt = 0; mt < 4; mt++) {
                int r0 = wM * 64 + mt * 16 + g;
                a[mt][0] = __float_as_uint(As[cur][r0    ][ks * 8 + tg]);
                a[mt][1] = __float_as_uint(As[cur][r0 + 8][ks * 8 + tg]);
                a[mt][2] = __float_as_uint(As[cur][r0    ][ks * 8 + tg + 4]);
                a[mt][3] = __float_as_uint(As[cur][r0 + 8][ks * 8 + tg + 4]);
            }
            #pragma unroll
            for (int nt = 0; nt < 4; nt++) {
                int n0 = wN * 32 + nt * 8 + g;
                b[nt][0] = __float_as_uint(Ws[cur][n0][ks * 8 + tg]);
                b[nt][1] = __float_as_uint(Ws[cur][n0][ks * 8 + tg + 4]);
            }
            #pragma unroll
            for (int mt = 0; mt < 4; mt++)
                #pragma unroll
                for (int nt = 0; nt < 4; nt++) mma8(c[mt][nt], a[mt], b[nt]);
        }
        __syncthreads();
    }

    size_t row0 = (size_t)blockIdx.y * 128;
    int col0 = blockIdx.x * 128 + wN * 32;
    #pragma unroll
    for (int mt = 0; mt < 4; mt++)
        #pragma unroll
        for (int nt = 0; nt < 4; nt++)
            #pragma unroll
            for (int ep = 0; ep < 2; ep++) {
                size_t row = row0 + wM * 64 + mt * 16 + g + ep * 8;
                int col = col0 + nt * 8 + 2 * tg;
                float2 v;
                v.x = c[mt][nt][2 * ep]     + bias[col];
                v.y = c[mt][nt][2 * ep + 1] + bias[col + 1];
                *(float2*)&C[row * G3H_ + col] = v;
            }
}

// ---------------- persistent recurrence: warp-autonomous, no mainloop CTA syncs ----------------
__global__ __launch_bounds__(256) void k_rec_persist(
    const float* __restrict__ W,     // whh raw fp32 [3072][1024]
    const float* __restrict__ gx,    // [B][T][3H] fp32
    const float* __restrict__ bhh,   // [3H]
    float* __restrict__ hbuf,        // [2][B*H] ping-pong
    float* __restrict__ yout,        // [B][T][H] or nullptr
    float* __restrict__ outf,        // [B][H] final hidden (fp32)
    unsigned* __restrict__ flags) {
    extern __shared__ float smem[];
    float* Wp    = smem;                                   // packed weights
    float* As    = Wp + WP_WORDS;                          // per-warp stages
    float* gxs   = As + AS_WORDS;                          // per-warp [16][GX_ROW]
    float* holds = gxs + GX_WORDS;                         // per-warp [16][8]
    float* bhs   = holds + HOLD_WORDS;                     // [24]

    int tid = threadIdx.x;
    int lane = tid & 31, wid = tid >> 5;
    int g = lane >> 2, tg = lane & 3;
    int bid = blockIdx.x;
    int nb = bid * COLS;
    int wrow = wid * 16;                                   // warp's batch-row base

    // build fragment-packed resident weights:
    // Wp[(((kt*4+ks)*3+gt)*32+lane)*2 + {0,1}] = W[gt*H + nb + (lane>>2)][kt*32+ks*8+(lane&3) + {0,4}]
    for (int idx = tid; idx < WP_WORDS / 2; idx += 256) {
        int lane_ = idx & 31;
        int r = idx >> 5;
        int gt = r % 3;  r /= 3;
        int ks = r & 3;  int kt = r >> 2;
        int grow = gt * H_ + nb + (lane_ >> 2);
        int k = kt * BK + ks * 8 + (lane_ & 3);
        Wp[idx * 2]     = tf32r(W[(size_t)grow * H_ + k]);
        Wp[idx * 2 + 1] = tf32r(W[(size_t)grow * H_ + k + 4]);
    }
    if (tid < 24) bhs[tid] = bhh[(tid >> 3) * H_ + nb + (tid & 7)];
    __syncthreads();

    float* myA    = As + wid * (NSTG * ASTG_WORDS);
    float* mygx   = gxs + wid * (16 * GX_ROW);
    float* myhold = holds + wid * (16 * 8);

    for (int t = 0; t < T_; t++) {
        const float* hin = hbuf + (size_t)(t & 1) * (B_ * H_);
        float* hout = hbuf + (size_t)((t + 1) & 1) * (B_ * H_);
        const float* hrow = hin + (size_t)wrow * H_;

        float c[3][4];
        #pragma unroll
        for (int j = 0; j < 3; j++)
            #pragma unroll
            for (int e = 0; e < 4; e++) c[j][e] = 0.f;

        // ---- group for stage 0 + gx + holds (all per-warp) ----
        {
            #pragma unroll
            for (int i = 0; i < 4; i++) {
                int ch = lane + 32 * i;
                int r = ch >> 3, sg = ch & 7;
                cp16(myA + r * ASTG_ROW + sg * 4, hrow + (size_t)r * H_ + sg * 4);
            }
            #pragma unroll
            for (int i = 0; i < 3; i++) {
                int ch = lane + 32 * i;
                int r = ch / 6, j = ch % 6;            // j: 16B chunk within 24-float row
                cp16(mygx + r * GX_ROW + j * 4,
                     gx + (size_t)(wrow + r) * (T_ * G3H_) + (size_t)t * G3H_
                        + (j >> 1) * H_ + nb + (j & 1) * 4);
            }
            {
                int r = lane >> 1, hf = lane & 1;
                cp16(myhold + r * 8 + hf * 4, hrow + (size_t)r * H_ + nb + hf * 4);
            }
            cpcommit();
        }
        // ---- stages 1,2 ----
        #pragma unroll
        for (int s = 1; s < NSTG - 1; s++) {
            float* dst = myA + s * ASTG_WORDS;
            #pragma unroll
            for (int i = 0; i < 4; i++) {
                int ch = lane + 32 * i;
                int r = ch >> 3, sg = ch & 7;
                cp16(dst + r * ASTG_ROW + sg * 4, hrow + (size_t)r * H_ + s * BK + sg * 4);
            }
            cpcommit();
        }

        for (int kt = 0; kt < 32; kt++) {
            cpwait2();                                 // stage kt complete
            if (kt + 3 < 32) {                         // prefetch stage kt+3
                float* dst = myA + ((kt + 3) & 3) * ASTG_WORDS;
                #pragma unroll
                for (int i = 0; i < 4; i++) {
                    int ch = lane + 32 * i;
                    int r = ch >> 3, sg = ch & 7;
                    cp16(dst + r * ASTG_ROW + sg * 4,
                         hrow + (size_t)r * H_ + (kt + 3) * BK + sg * 4);
                }
            }
            cpcommit();                                // uniform group count

            const float* A = myA + (kt & 3) * ASTG_WORDS;
            #pragma unroll
            for (int ks = 0; ks < 4; ks++) {
                int ko = ks * 8;
                uint32_t a[4];
                a[0] = __float_as_uint(A[g * ASTG_ROW + ko + tg]);
                a[1] = __float_as_uint(A[(g + 8) * ASTG_ROW + ko + tg]);
                a[2] = __float_as_uint(A[g * ASTG_ROW + ko + tg + 4]);
                a[3] = __float_as_uint(A[(g + 8) * ASTG_ROW + ko + tg + 4]);
                #pragma unroll
                for (int gt = 0; gt < 3; gt++) {
                    float2 bv = *(const float2*)&Wp[(((kt * 4 + ks) * 3 + gt) * 32 + lane) * 2];
                    uint32_t b[2] = { __float_as_uint(bv.x), __float_as_uint(bv.y) };
                    mma8(c[gt], a, b);
                }
            }
        }

        // ---- per-warp epilogue: fused GRU pointwise, all operands SMEM/regs ----
        #pragma unroll
        for (int ep = 0; ep < 2; ep++) {
            int lrow = g + ep * 8;
            int row = wrow + lrow;
            float2 hv;
            #pragma unroll
            for (int hf = 0; hf < 2; hf++) {
                int e = 2 * ep + hf;
                int lc = 2 * tg + hf;
                float xr = mygx[lrow * GX_ROW + lc];
                float xz = mygx[lrow * GX_ROW + 8 + lc];
                float xn = mygx[lrow * GX_ROW + 16 + lc];
                float hr = c[0][e] + bhs[lc];
                float hz = c[1][e] + bhs[8 + lc];
                float hn = c[2][e] + bhs[16 + lc];
                float rr = 1.f / (1.f + expf(-(xr + hr)));
                float zz = 1.f / (1.f + expf(-(xz + hz)));
                float nn = tanhf(xn + rr * hn);
                float hold = myhold[lrow * 8 + lc];
                float hnew = (1.f - zz) * nn + zz * hold;
                (hf ? hv.y : hv.x) = hnew;
            }
            int col = nb + 2 * tg;
            float2 hq = { tf32r(hv.x), tf32r(hv.y) };
            *(float2*)&hout[(size_t)row * H_ + col] = hq;
            if (yout) *(float2*)&yout[(size_t)row * (T_ * H_) + (size_t)t * H_ + col] = hq;
            if (t == T_ - 1) *(float2*)&outf[(size_t)row * H_ + col] = hv;
        }

        if (t != T_ - 1) flag_barrier(flags, bid, wid, lane, (unsigned)(t + 1));
    }
}

// ---------------- launch ----------------
extern "C" void kernel_launch(void* const* d_in, const int* in_sizes, int n_in,
                              void* d_out, int out_size) {
    const int*   src  = (const int*)d_in[0];
    const float* emb  = (const float*)d_in[1];
    const float* wih0 = (const float*)d_in[2];
    const float* whh0 = (const float*)d_in[3];
    const float* bih0 = (const float*)d_in[4];
    const float* bhh0 = (const float*)d_in[5];
    const float* wih1 = (const float*)d_in[6];
    const float* whh1 = (const float*)d_in[7];
    const float* bih1 = (const float*)d_in[8];
    const float* bhh1 = (const float*)d_in[9];
    float* out = (float*)d_out;

    float *x0, *y0, *gx0, *gx1, *pwih0, *pwih1, *h0, *h1;
    unsigned *fl0, *fl1;
    cudaGetSymbolAddress((void**)&x0,    g_x0);
    cudaGetSymbolAddress((void**)&y0,    g_y0);
    cudaGetSymbolAddress((void**)&gx0,   g_gx0);
    cudaGetSymbolAddress((void**)&gx1,   g_gx1);
    cudaGetSymbolAddress((void**)&pwih0, g_wih0);
    cudaGetSymbolAddress((void**)&pwih1, g_wih1);
    cudaGetSymbolAddress((void**)&h0,    g_h0);
    cudaGetSymbolAddress((void**)&h1,    g_h1);
    cudaGetSymbolAddress((void**)&fl0,   g_flags0);
    cudaGetSymbolAddress((void**)&fl1,   g_flags1);

    cudaFuncSetAttribute(k_rec_persist, cudaFuncAttributeMaxDynamicSharedMemorySize, REC_SMEM);

    // launch order keeps k_rec_persist at my-launch-index 3 for the ncu -s 5 window
    k_setup<<<2048, 256>>>(wih0, wih1);                       // 0
    k_gather<<<NROW, 128>>>(src, emb, x0);                    // 1
    k_gemm<<<dim3(24, 512), 256>>>(x0, pwih0, bih0, gx0, E_); // 2
    k_rec_persist<<<NCTA, 256, REC_SMEM>>>(whh0, gx0, bhh0, h0, y0, out, fl0);       // 3
    k_gemm<<<dim3(24, 512), 256>>>(y0, pwih1, bih1, gx1, H_); // 4
    k_rec_persist<<<NCTA, 256, REC_SMEM>>>(whh1, gx1, bhh1, h1, nullptr, out + B_ * H_, fl1); // 5
}

// round 6
// speedup vs baseline: 2.0391x; 1.1773x over previous
#include <cuda_runtime.h>
#include <cuda_fp16.h>
#include <cstdint>

#define B_   128
#define T_   512
#define E_   512
#define H_   1024
#define G3H_ 3072
#define NROW 65536   // B*T

#define NCTA 128     // CTAs in persistent recurrence
#define COLS 8       // h-columns per CTA
#define BK   32      // k per stage (fp16 elems)
#define NSTG 4       // per-warp stages

// recurrence SMEM layout (4B words)
#define WP_W    12288                 // packed fp16 weights: 6144 entries x 2 words
#define ASTG_ROW 20                   // words per A row (32 fp16 + pad)
#define ASTG_W  (16*ASTG_ROW)         // 320 words per stage
#define AS_W    (8*NSTG*ASTG_W)       // 10240
#define GX_ROW  24
#define GX_W    (8*16*GX_ROW)         // 3072 (fp32)
#define HOLD_W  512                   // 8 warps x 16 rows x 8 fp16
#define REC_WORDS (WP_W + AS_W + GX_W + HOLD_W + 32)
#define REC_SMEM  (REC_WORDS * 4)

// gemm SMEM: 3 stages x 2 tiles x 128 rows x 20 words
#define GEMM_SMEM (3 * 2 * 128 * 20 * 4)

// ---------------- device scratch ----------------
__device__ __half g_x0 [(size_t)NROW * E_];
__device__ __half g_y0 [(size_t)NROW * H_];
__device__ float  g_gx0[(size_t)NROW * G3H_];
__device__ float  g_gx1[(size_t)NROW * G3H_];
__device__ __half g_wih0[G3H_ * E_];
__device__ __half g_wih1[G3H_ * H_];
__device__ __half g_h0[2][B_ * H_];
__device__ __half g_h1[2][B_ * H_];
__device__ unsigned g_flags0[NCTA * 32];
__device__ unsigned g_flags1[NCTA * 32];

// ---------------- helpers ----------------
__device__ __forceinline__ void cp16(void* s, const void* g) {
    uint32_t sa = (uint32_t)__cvta_generic_to_shared(s);
    asm volatile("cp.async.cg.shared.global [%0], [%1], 16;" :: "r"(sa), "l"(g));
}
__device__ __forceinline__ void cpcommit() { asm volatile("cp.async.commit_group;"); }
__device__ __forceinline__ void cpwait2()  { asm volatile("cp.async.wait_group 2;"); }

__device__ __forceinline__ void mma16(float c[4], const uint32_t a[4], const uint32_t b[2]) {
    asm volatile(
        "mma.sync.aligned.m16n8k16.row.col.f32.f16.f16.f32 "
        "{%0,%1,%2,%3}, {%4,%5,%6,%7}, {%8,%9}, {%0,%1,%2,%3};"
        : "+f"(c[0]), "+f"(c[1]), "+f"(c[2]), "+f"(c[3])
        : "r"(a[0]), "r"(a[1]), "r"(a[2]), "r"(a[3]), "r"(b[0]), "r"(b[1]));
}

__device__ __forceinline__ float tanh_ap(float x) {
    float y;
    asm("tanh.approx.f32 %0, %1;" : "=f"(y) : "f"(x));
    return y;
}
__device__ __forceinline__ float sigm_ap(float x) {
    return 0.5f + 0.5f * tanh_ap(0.5f * x);
}

// distributed-flag grid barrier
__device__ __forceinline__ void flag_barrier(unsigned* flags, int bid, int wid, int lane,
                                             unsigned target) {
    __syncthreads();
    if (wid == 0) {
        if (lane == 0)
            asm volatile("st.release.gpu.global.u32 [%0], %1;"
                         :: "l"(flags + bid * 32), "r"(target) : "memory");
        unsigned ok;
        do {
            ok = 1u;
            #pragma unroll
            for (int i = 0; i < 4; i++) {
                unsigned v;
                asm volatile("ld.acquire.gpu.global.u32 %0, [%1];"
                             : "=r"(v) : "l"(flags + (lane + 32 * i) * 32) : "memory");
                ok &= (v >= target) ? 1u : 0u;
            }
        } while (!__all_sync(0xffffffffu, ok));
    }
    __syncthreads();
}

// ---------------- setup: fp16-convert wih, zero h, reset flags ----------------
__global__ void k_setup(const float* __restrict__ wih0, const float* __restrict__ wih1) {
    int stride = gridDim.x * blockDim.x;
    for (int i = blockIdx.x * blockDim.x + threadIdx.x; i < G3H_ * H_; i += stride) {
        if (i < G3H_ * E_) g_wih0[i] = __float2half_rn(wih0[i]);
        g_wih1[i] = __float2half_rn(wih1[i]);
        if (i < 2 * B_ * H_) {
            (&g_h0[0][0])[i] = __float2half_rn(0.f);
            (&g_h1[0][0])[i] = __float2half_rn(0.f);
        }
        if (i < NCTA * 32) { g_flags0[i] = 0u; g_flags1[i] = 0u; }
    }
}

__global__ void k_gather(const int* __restrict__ src, const float* __restrict__ emb,
                         __half* __restrict__ x0) {
    int row = blockIdx.x;
    int v = src[row];
    const float* e = emb + (size_t)v * E_;
    __half* o = x0 + (size_t)row * E_;
    for (int j = threadIdx.x; j < E_; j += blockDim.x) o[j] = __float2half_rn(e[j]);
}

// ---------------- big GEMM (fp16 m16n8k16): C[M,3072] = A[M,K]*W[3072,K]^T + bias ----------------
__device__ __forceinline__ void gemm_load(uint32_t* As, uint32_t* Ws,
                                          const __half* Ab, const __half* Wb,
                                          int K, int kt, int tid) {
    #pragma unroll
    for (int i = 0; i < 2; i++) {
        int id = tid + 256 * i;
        int r = id >> 2, s = id & 3;
        cp16(As + r * 20 + s * 4, Ab + (size_t)r * K + kt * BK + s * 8);
        cp16(Ws + r * 20 + s * 4, Wb + (size_t)r * K + kt * BK + s * 8);
    }
    cpcommit();
}

__global__ __launch_bounds__(256) void k_gemm(const __half* __restrict__ A,
                                              const __half* __restrict__ W,
                                              const float* __restrict__ bias,
                                              float* __restrict__ C, int K) {
    extern __shared__ uint32_t gsm[];
    // stage s: A tile at gsm + s*5120, W tile at +2560
    int tid = threadIdx.x;
    int lane = tid & 31, wid = tid >> 5;
    int g = lane >> 2, tg = lane & 3;
    int wM = wid & 1, wN = wid >> 1;
    const __half* Ab = A + (size_t)blockIdx.y * 128 * K;
    const __half* Wb = W + (size_t)blockIdx.x * 128 * K;

    float c[4][4][4];
    #pragma unroll
    for (int i = 0; i < 4; i++)
        #pragma unroll
        for (int j = 0; j < 4; j++)
            #pragma unroll
            for (int e = 0; e < 4; e++) c[i][j][e] = 0.f;

    int KIT = K / BK;
    gemm_load(gsm, gsm + 2560, Ab, Wb, K, 0, tid);
    gemm_load(gsm + 5120, gsm + 5120 + 2560, Ab, Wb, K, 1, tid);

    for (int kt = 0; kt < KIT; kt++) {
        asm volatile("cp.async.wait_group 1;");
        __syncthreads();
        if (kt + 2 < KIT) {
            uint32_t* st = gsm + ((kt + 2) % 3) * 5120;
            gemm_load(st, st + 2560, Ab, Wb, K, kt + 2, tid);
        } else cpcommit();
        uint32_t* As = gsm + (kt % 3) * 5120;
        uint32_t* Ws = As + 2560;
        #pragma unroll
        for (int ch = 0; ch < 2; ch++) {
            int co = ch * 8;
            uint32_t a[4][4], b[4][2];
            #pragma unroll
            for (int mt = 0; mt < 4; mt++) {
                int r0 = wM * 64 + mt * 16 + g;
                a[mt][0] = As[r0 * 20 + co + tg];
                a[mt][1] = As[(r0 + 8) * 20 + co + tg];
                a[mt][2] = As[r0 * 20 + co + tg + 4];
                a[mt][3] = As[(r0 + 8) * 20 + co + tg + 4];
            }
            #pragma unroll
            for (int nt = 0; nt < 4; nt++) {
                int n0 = wN * 32 + nt * 8 + g;
                b[nt][0] = Ws[n0 * 20 + co + tg];
                b[nt][1] = Ws[n0 * 20 + co + tg + 4];
            }
            #pragma unroll
            for (int mt = 0; mt < 4; mt++)
                #pragma unroll
                for (int nt = 0; nt < 4; nt++) mma16(c[mt][nt], a[mt], b[nt]);
        }
        __syncthreads();
    }

    size_t row0 = (size_t)blockIdx.y * 128;
    int col0 = blockIdx.x * 128 + wN * 32;
    #pragma unroll
    for (int mt = 0; mt < 4; mt++)
        #pragma unroll
        for (int nt = 0; nt < 4; nt++)
            #pragma unroll
            for (int ep = 0; ep < 2; ep++) {
                size_t row = row0 + wM * 64 + mt * 16 + g + ep * 8;
                int col = col0 + nt * 8 + 2 * tg;
                float2 v;
                v.x = c[mt][nt][2 * ep]     + bias[col];
                v.y = c[mt][nt][2 * ep + 1] + bias[col + 1];
                *(float2*)&C[row * G3H_ + col] = v;
            }
}

// ---------------- persistent recurrence (fp16 MMA, warp-autonomous) ----------------
__global__ __launch_bounds__(256) void k_rec_persist(
    const float* __restrict__ W,      // whh raw fp32 [3072][1024]
    const float* __restrict__ gx,     // [B][T][3H] fp32
    const float* __restrict__ bhh,    // [3H]
    __half* __restrict__ hbuf,        // [2][B*H] ping-pong fp16
    __half* __restrict__ yout,        // [B][T][H] fp16 or nullptr
    float* __restrict__ outf,         // [B][H] final hidden fp32
    unsigned* __restrict__ flags) {
    extern __shared__ uint32_t smw[];
    uint32_t* Wp    = smw;                       // packed fp16 weights
    uint32_t* As    = Wp + WP_W;                 // per-warp A stages (fp16 pairs)
    float*    gxs   = (float*)(As + AS_W);       // per-warp [16][GX_ROW] fp32
    __half*   holds = (__half*)(gxs + GX_W);     // per-warp [16][8] fp16
    float*    bhs   = (float*)(holds + 2 * HOLD_W);  // [24] fp32

    int tid = threadIdx.x;
    int lane = tid & 31, wid = tid >> 5;
    int g = lane >> 2, tg = lane & 3;
    int bid = blockIdx.x;
    int nb = bid * COLS;
    int wrow = wid * 16;

    // pack resident weights: entry e = ((kt*2+chunk)*3+gt)*32+lane -> 2 words
    // word0 = fp16{W[n][k], W[n][k+1]}, word1 = fp16{W[n][k+8], W[n][k+9]}
    // n = gt*H + nb + (lane>>2), k = kt*32 + chunk*16 + 2*(lane&3)
    for (int e = tid; e < 6144; e += 256) {
        int lane_ = e & 31;
        int r = e >> 5;
        int gt = r % 3; r /= 3;
        int ch = r & 1; int kt = r >> 1;
        int n = gt * H_ + nb + (lane_ >> 2);
        int k = kt * BK + ch * 16 + 2 * (lane_ & 3);
        const float* wr = W + (size_t)n * H_;
        __half2 w0 = __floats2half2_rn(wr[k],     wr[k + 1]);
        __half2 w1 = __floats2half2_rn(wr[k + 8], wr[k + 9]);
        Wp[e * 2]     = *(uint32_t*)&w0;
        Wp[e * 2 + 1] = *(uint32_t*)&w1;
    }
    if (tid < 24) bhs[tid] = bhh[(tid >> 3) * H_ + nb + (tid & 7)];
    __syncthreads();

    uint32_t* myA    = As + wid * (NSTG * ASTG_W);
    float*    mygx   = gxs + wid * (16 * GX_ROW);
    __half*   myhold = holds + wid * (16 * 8);

    for (int t = 0; t < T_; t++) {
        const __half* hin = hbuf + (size_t)(t & 1) * (B_ * H_);
        __half* hout = hbuf + (size_t)((t + 1) & 1) * (B_ * H_);
        const __half* hrow = hin + (size_t)wrow * H_;

        float c[3][4];
        #pragma unroll
        for (int j = 0; j < 3; j++)
            #pragma unroll
            for (int e = 0; e < 4; e++) c[j][e] = 0.f;

        // group 0: stage 0 (16 rows x 32 fp16) + gx (fp32) + holds (fp16)
        {
            #pragma unroll
            for (int i = 0; i < 2; i++) {
                int ch = lane + 32 * i;
                int r = ch >> 2, s = ch & 3;
                cp16(myA + r * ASTG_ROW + s * 4, hrow + (size_t)r * H_ + s * 8);
            }
            #pragma unroll
            for (int i = 0; i < 3; i++) {
                int ch = lane + 32 * i;
                int r = ch / 6, j = ch % 6;
                cp16(mygx + r * GX_ROW + j * 4,
                     gx + (size_t)(wrow + r) * (T_ * G3H_) + (size_t)t * G3H_
                        + (j >> 1) * H_ + nb + (j & 1) * 4);
            }
            if (lane < 16)
                cp16(myhold + lane * 8, hrow + (size_t)lane * H_ + nb);
            cpcommit();
        }
        // stages 1,2
        #pragma unroll
        for (int s = 1; s < NSTG - 1; s++) {
            uint32_t* dst = myA + s * ASTG_W;
            #pragma unroll
            for (int i = 0; i < 2; i++) {
                int ch = lane + 32 * i;
                int r = ch >> 2, sc = ch & 3;
                cp16(dst + r * ASTG_ROW + sc * 4, hrow + (size_t)r * H_ + s * BK + sc * 8);
            }
            cpcommit();
        }

        for (int kt = 0; kt < 32; kt++) {
            cpwait2();
            if (kt + 3 < 32) {
                uint32_t* dst = myA + ((kt + 3) & 3) * ASTG_W;
                #pragma unroll
                for (int i = 0; i < 2; i++) {
                    int ch = lane + 32 * i;
                    int r = ch >> 2, sc = ch & 3;
                    cp16(dst + r * ASTG_ROW + sc * 4,
                         hrow + (size_t)r * H_ + (kt + 3) * BK + sc * 8);
                }
            }
            cpcommit();

            const uint32_t* A = myA + (kt & 3) * ASTG_W;
            #pragma unroll
            for (int ch = 0; ch < 2; ch++) {
                int co = ch * 8;
                uint32_t a[4];
                a[0] = A[g * ASTG_ROW + co + tg];
                a[1] = A[(g + 8) * ASTG_ROW + co + tg];
                a[2] = A[g * ASTG_ROW + co + tg + 4];
                a[3] = A[(g + 8) * ASTG_ROW + co + tg + 4];
                #pragma unroll
                for (int gt = 0; gt < 3; gt++) {
                    const uint32_t* bp = Wp + (((kt * 2 + ch) * 3 + gt) * 32 + lane) * 2;
                    uint2 bv = *(const uint2*)bp;
                    uint32_t b[2] = { bv.x, bv.y };
                    mma16(c[gt], a, b);
                }
            }
        }

        // per-warp epilogue: fused GRU pointwise
        #pragma unroll
        for (int ep = 0; ep < 2; ep++) {
            int lrow = g + ep * 8;
            int row = wrow + lrow;
            float2 hv;
            #pragma unroll
            for (int hf = 0; hf < 2; hf++) {
                int e = 2 * ep + hf;
                int lc = 2 * tg + hf;
                float xr = mygx[lrow * GX_ROW + lc];
                float xz = mygx[lrow * GX_ROW + 8 + lc];
                float xn = mygx[lrow * GX_ROW + 16 + lc];
                float hr = c[0][e] + bhs[lc];
                float hz = c[1][e] + bhs[8 + lc];
                float hn = c[2][e] + bhs[16 + lc];
                float rr = sigm_ap(xr + hr);
                float zz = sigm_ap(xz + hz);
                float nn = tanh_ap(xn + rr * hn);
                float hold = __half2float(myhold[lrow * 8 + lc]);
                float hnew = (1.f - zz) * nn + zz * hold;
                (hf ? hv.y : hv.x) = hnew;
            }
            int col = nb + 2 * tg;
            __half2 hq = __floats2half2_rn(hv.x, hv.y);
            *(__half2*)&hout[(size_t)row * H_ + col] = hq;
            if (yout) *(__half2*)&yout[(size_t)row * (T_ * H_) + (size_t)t * H_ + col] = hq;
            if (t == T_ - 1) *(float2*)&outf[(size_t)row * H_ + col] = hv;
        }

        if (t != T_ - 1) flag_barrier(flags, bid, wid, lane, (unsigned)(t + 1));
    }
}

// ---------------- launch ----------------
extern "C" void kernel_launch(void* const* d_in, const int* in_sizes, int n_in,
                              void* d_out, int out_size) {
    const int*   src  = (const int*)d_in[0];
    const float* emb  = (const float*)d_in[1];
    const float* wih0 = (const float*)d_in[2];
    const float* whh0 = (const float*)d_in[3];
    const float* bih0 = (const float*)d_in[4];
    const float* bhh0 = (const float*)d_in[5];
    const float* wih1 = (const float*)d_in[6];
    const float* whh1 = (const float*)d_in[7];
    const float* bih1 = (const float*)d_in[8];
    const float* bhh1 = (const float*)d_in[9];
    float* out = (float*)d_out;

    __half *x0, *y0, *pwih0, *pwih1, *h0, *h1;
    float *gx0, *gx1;
    unsigned *fl0, *fl1;
    cudaGetSymbolAddress((void**)&x0,    g_x0);
    cudaGetSymbolAddress((void**)&y0,    g_y0);
    cudaGetSymbolAddress((void**)&gx0,   g_gx0);
    cudaGetSymbolAddress((void**)&gx1,   g_gx1);
    cudaGetSymbolAddress((void**)&pwih0, g_wih0);
    cudaGetSymbolAddress((void**)&pwih1, g_wih1);
    cudaGetSymbolAddress((void**)&h0,    g_h0);
    cudaGetSymbolAddress((void**)&h1,    g_h1);
    cudaGetSymbolAddress((void**)&fl0,   g_flags0);
    cudaGetSymbolAddress((void**)&fl1,   g_flags1);

    cudaFuncSetAttribute(k_rec_persist, cudaFuncAttributeMaxDynamicSharedMemorySize, REC_SMEM);
    cudaFuncSetAttribute(k_gemm, cudaFuncAttributeMaxDynamicSharedMemorySize, GEMM_SMEM);

    // launch order keeps k_rec_persist at my-launch-index 3 for the ncu -s 5 window
    k_setup<<<2048, 256>>>(wih0, wih1);                                   // 0
    k_gather<<<NROW, 128>>>(src, emb, x0);                                // 1
    k_gemm<<<dim3(24, 512), 256, GEMM_SMEM>>>(x0, pwih0, bih0, gx0, E_);  // 2
    k_rec_persist<<<NCTA, 256, REC_SMEM>>>(whh0, gx0, bhh0, h0, y0, out, fl0);        // 3
    k_gemm<<<dim3(24, 512), 256, GEMM_SMEM>>>(y0, pwih1, bih1, gx1, H_);  // 4
    k_rec_persist<<<NCTA, 256, REC_SMEM>>>(whh1, gx1, bhh1, h1, nullptr, out + B_ * H_, fl1); // 5
}

// round 8
// speedup vs baseline: 3.3596x; 1.6476x over previous
#include <cuda_runtime.h>
#include <cuda_fp16.h>
#include <cstdint>

#define B_   128
#define T_   512
#define E_   512
#define H_   1024
#define G3H_ 3072
#define NROW 65536   // B*T

#define NCTA 128     // CTAs in persistent recurrence
#define COLS 8       // h-columns per CTA
#define THR  512     // threads in recurrence CTA (16 warps: 8 M-slices x 2 K-halves)
#define BK   64      // k per stage
#define NKT  8       // stages consumed per K-half (512/64)

// ---- recurrence SMEM layout (bytes) ----
#define WP_OFF   0                       // packed fp16 weights: 6144 entries x 8B = 48KB
#define AS_OFF   49152                   // 16 warps x 3 stages x 2304B
#define ASTG     2304                    // stage: 16 rows x (128B data + 16B pad)
#define AWARP    (3 * ASTG)
#define GX_OFF   (49152 + 110592)        // 159744: 128 rows x 112B (24 fp32 + pad)
#define GX_ROWB  112
#define HOLD_OFF (GX_OFF + 14336)        // 174080: 128 rows x 16B (8 fp16)
#define BIAS_OFF (HOLD_OFF + 2048)       // 176128: 24 fp32 (+pad)
#define SCR_OFF  (BIAS_OFF + 128)        // 176256: 256 threads x 12 fp32 partials
#define REC_SMEM (SCR_OFF + 12288)       // 188544

#define GEMM_SMEM (3 * 2 * 128 * 20 * 4)

// ---------------- device scratch ----------------
__device__ __half g_x0 [(size_t)NROW * E_];
__device__ __half g_y0 [(size_t)NROW * H_];
__device__ float  g_gx0[(size_t)NROW * G3H_];
__device__ float  g_gx1[(size_t)NROW * G3H_];
__device__ __half g_wih0[G3H_ * E_];
__device__ __half g_wih1[G3H_ * H_];
__device__ __half g_h0[2][B_ * H_];
__device__ __half g_h1[2][B_ * H_];
__device__ unsigned g_flags0[NCTA * 32];
__device__ unsigned g_flags1[NCTA * 32];

// ---------------- helpers ----------------
__device__ __forceinline__ void cp16(void* s, const void* g) {
    uint32_t sa = (uint32_t)__cvta_generic_to_shared(s);
    asm volatile("cp.async.cg.shared.global [%0], [%1], 16;" :: "r"(sa), "l"(g));
}
__device__ __forceinline__ void cpcommit() { asm volatile("cp.async.commit_group;"); }

__device__ __forceinline__ void mma16(float c[4], const uint32_t a[4], const uint32_t b[2]) {
    asm volatile(
        "mma.sync.aligned.m16n8k16.row.col.f32.f16.f16.f32 "
        "{%0,%1,%2,%3}, {%4,%5,%6,%7}, {%8,%9}, {%0,%1,%2,%3};"
        : "+f"(c[0]), "+f"(c[1]), "+f"(c[2]), "+f"(c[3])
        : "r"(a[0]), "r"(a[1]), "r"(a[2]), "r"(a[3]), "r"(b[0]), "r"(b[1]));
}

__device__ __forceinline__ float tanh_ap(float x) {
    float y;
    asm("tanh.approx.f32 %0, %1;" : "=f"(y) : "f"(x));
    return y;
}
__device__ __forceinline__ float sigm_ap(float x) {
    return 0.5f + 0.5f * tanh_ap(0.5f * x);
}

// parallel-poll grid barrier: 1 writer, 128 pollers (one flag each)
__device__ __forceinline__ void flag_barrier(unsigned* flags, int bid, int tid,
                                             unsigned target) {
    __syncthreads();
    if (tid == 0)
        asm volatile("st.release.gpu.global.u32 [%0], %1;"
                     :: "l"(flags + bid * 32), "r"(target) : "memory");
    if (tid < NCTA) {
        unsigned v;
        do {
            asm volatile("ld.acquire.gpu.global.u32 %0, [%1];"
                         : "=r"(v) : "l"(flags + tid * 32) : "memory");
        } while (v < target);
    }
    __syncthreads();
}

// ---------------- setup: fp16-convert wih, zero h, reset flags ----------------
__global__ void k_setup(const float* __restrict__ wih0, const float* __restrict__ wih1) {
    int stride = gridDim.x * blockDim.x;
    for (int i = blockIdx.x * blockDim.x + threadIdx.x; i < G3H_ * H_; i += stride) {
        if (i < G3H_ * E_) g_wih0[i] = __float2half_rn(wih0[i]);
        g_wih1[i] = __float2half_rn(wih1[i]);
        if (i < 2 * B_ * H_) {
            (&g_h0[0][0])[i] = __float2half_rn(0.f);
            (&g_h1[0][0])[i] = __float2half_rn(0.f);
        }
        if (i < NCTA * 32) { g_flags0[i] = 0u; g_flags1[i] = 0u; }
    }
}

__global__ void k_gather(const int* __restrict__ src, const float* __restrict__ emb,
                         __half* __restrict__ x0) {
    int row = blockIdx.x;
    int v = src[row];
    const float* e = emb + (size_t)v * E_;
    __half* o = x0 + (size_t)row * E_;
    for (int j = threadIdx.x; j < E_; j += blockDim.x) o[j] = __float2half_rn(e[j]);
}

// ---------------- big GEMM (fp16 m16n8k16): C[M,3072] = A[M,K]*W[3072,K]^T + bias ----------------
__device__ __forceinline__ void gemm_load(uint32_t* As, uint32_t* Ws,
                                          const __half* Ab, const __half* Wb,
                                          int K, int kt, int tid) {
    #pragma unroll
    for (int i = 0; i < 2; i++) {
        int id = tid + 256 * i;
        int r = id >> 2, s = id & 3;
        cp16(As + r * 20 + s * 4, Ab + (size_t)r * K + kt * 32 + s * 8);
        cp16(Ws + r * 20 + s * 4, Wb + (size_t)r * K + kt * 32 + s * 8);
    }
    cpcommit();
}

__global__ __launch_bounds__(256) void k_gemm(const __half* __restrict__ A,
                                              const __half* __restrict__ W,
                                              const float* __restrict__ bias,
                                              float* __restrict__ C, int K) {
    extern __shared__ uint32_t gsm[];
    int tid = threadIdx.x;
    int lane = tid & 31, wid = tid >> 5;
    int g = lane >> 2, tg = lane & 3;
    int wM = wid & 1, wN = wid >> 1;
    const __half* Ab = A + (size_t)blockIdx.y * 128 * K;
    const __half* Wb = W + (size_t)blockIdx.x * 128 * K;

    float c[4][4][4];
    #pragma unroll
    for (int i = 0; i < 4; i++)
        #pragma unroll
        for (int j = 0; j < 4; j++)
            #pragma unroll
            for (int e = 0; e < 4; e++) c[i][j][e] = 0.f;

    int KIT = K / 32;
    gemm_load(gsm, gsm + 2560, Ab, Wb, K, 0, tid);
    gemm_load(gsm + 5120, gsm + 5120 + 2560, Ab, Wb, K, 1, tid);

    for (int kt = 0; kt < KIT; kt++) {
        asm volatile("cp.async.wait_group 1;");
        __syncthreads();
        if (kt + 2 < KIT) {
            uint32_t* st = gsm + ((kt + 2) % 3) * 5120;
            gemm_load(st, st + 2560, Ab, Wb, K, kt + 2, tid);
        } else cpcommit();
        uint32_t* As = gsm + (kt % 3) * 5120;
        uint32_t* Ws = As + 2560;
        #pragma unroll
        for (int ch = 0; ch < 2; ch++) {
            int co = ch * 8;
            uint32_t a[4][4], b[4][2];
            #pragma unroll
            for (int mt = 0; mt < 4; mt++) {
                int r0 = wM * 64 + mt * 16 + g;
                a[mt][0] = As[r0 * 20 + co + tg];
                a[mt][1] = As[(r0 + 8) * 20 + co + tg];
                a[mt][2] = As[r0 * 20 + co + tg + 4];
                a[mt][3] = As[(r0 + 8) * 20 + co + tg + 4];
            }
            #pragma unroll
            for (int nt = 0; nt < 4; nt++) {
                int n0 = wN * 32 + nt * 8 + g;
                b[nt][0] = Ws[n0 * 20 + co + tg];
                b[nt][1] = Ws[n0 * 20 + co + tg + 4];
            }
            #pragma unroll
            for (int mt = 0; mt < 4; mt++)
                #pragma unroll
                for (int nt = 0; nt < 4; nt++) mma16(c[mt][nt], a[mt], b[nt]);
        }
        __syncthreads();
    }

    size_t row0 = (size_t)blockIdx.y * 128;
    int col0 = blockIdx.x * 128 + wN * 32;
    #pragma unroll
    for (int mt = 0; mt < 4; mt++)
        #pragma unroll
        for (int nt = 0; nt < 4; nt++)
            #pragma unroll
            for (int ep = 0; ep < 2; ep++) {
                size_t row = row0 + wM * 64 + mt * 16 + g + ep * 8;
                int col = col0 + nt * 8 + 2 * tg;
                float2 v;
                v.x = c[mt][nt][2 * ep]     + bias[col];
                v.y = c[mt][nt][2 * ep + 1] + bias[col + 1];
                *(float2*)&C[row * G3H_ + col] = v;
            }
}

// ---------------- persistent recurrence: 16 warps, K-split, warp-autonomous ----------------
__global__ __launch_bounds__(THR, 1) void k_rec_persist(
    const float* __restrict__ W,      // whh raw fp32 [3072][1024]
    const float* __restrict__ gx,     // [B][T][3H] fp32
    const float* __restrict__ bhh,    // [3H]
    __half* __restrict__ hbuf,        // [2][B*H] ping-pong fp16
    __half* __restrict__ yout,        // [B][T][H] fp16 or nullptr
    float* __restrict__ outf,         // [B][H] final hidden fp32
    unsigned* __restrict__ flags) {
    extern __shared__ char smc[];
    uint32_t* Wp  = (uint32_t*)(smc + WP_OFF);
    float*    gxs = (float*)(smc + GX_OFF);
    __half*   hds = (__half*)(smc + HOLD_OFF);
    float*    bhs = (float*)(smc + BIAS_OFF);
    float*    scr = (float*)(smc + SCR_OFF);

    int tid = threadIdx.x;
    int lane = tid & 31, wid = tid >> 5;
    int g = lane >> 2, tg = lane & 3;
    int wM = wid & 7;                  // batch slice (16 rows)
    int kh = wid >> 3;                 // K half
    int bid = blockIdx.x;
    int nb = bid * COLS;

    // pack resident weights: entry e = (k16*3+gt)*32+lane -> 2 words
    // word0 = fp16{W[n][k], W[n][k+1]}, word1 = fp16{W[n][k+8], W[n][k+9]}
    // n = gt*H + nb + (lane>>2), k = k16*16 + 2*(lane&3)
    for (int e = tid; e < 6144; e += THR) {
        int lane_ = e & 31;
        int r = e >> 5;
        int gt = r % 3;
        int k16 = r / 3;
        int n = gt * H_ + nb + (lane_ >> 2);
        int k = k16 * 16 + 2 * (lane_ & 3);
        const float* wr = W + (size_t)n * H_;
        __half2 w0 = __floats2half2_rn(wr[k],     wr[k + 1]);
        __half2 w1 = __floats2half2_rn(wr[k + 8], wr[k + 9]);
        Wp[e * 2]     = *(uint32_t*)&w0;
        Wp[e * 2 + 1] = *(uint32_t*)&w1;
    }
    if (tid < 24) bhs[tid] = bhh[(tid >> 3) * H_ + nb + (tid & 7)];
    __syncthreads();

    char* myA = smc + AS_OFF + wid * AWARP;
    // per-thread stage-load map: 4 chunks of 16B (16 rows x 128B per stage)
    int srcOff[4]; int dstOff[4];
    #pragma unroll
    for (int i = 0; i < 4; i++) {
        int ch = lane + 32 * i;
        int r = ch >> 3, cc = ch & 7;
        srcOff[i] = r * H_ + kh * 512 + cc * 8;     // fp16 elements
        dstOff[i] = r * 144 + cc * 16;              // bytes within stage
    }

    for (int t = 0; t < T_; t++) {
        const __half* hin = hbuf + (size_t)(t & 1) * (B_ * H_);
        __half* hout = hbuf + (size_t)((t + 1) & 1) * (B_ * H_);
        const __half* hwarp = hin + (size_t)(wM * 16) * H_;

        float c[3][4];
        #pragma unroll
        for (int j = 0; j < 3; j++)
            #pragma unroll
            for (int e = 0; e < 4; e++) c[j][e] = 0.f;

        // group 0: stage 0 + gx tile + holds
        {
            #pragma unroll
            for (int i = 0; i < 4; i++)
                cp16(myA + dstOff[i], hwarp + srcOff[i]);
            #pragma unroll
            for (int i = 0; i < 2; i++) {
                int idx = tid + THR * i;
                if (idx < 768) {
                    int row = idx / 6, part = idx % 6;
                    cp16(smc + GX_OFF + row * GX_ROWB + (part >> 1) * 32 + (part & 1) * 16,
                         gx + (size_t)row * (T_ * G3H_) + (size_t)t * G3H_
                            + (part >> 1) * H_ + nb + (part & 1) * 4);
                }
            }
            if (tid < 128)
                cp16(smc + HOLD_OFF + tid * 16, hin + (size_t)tid * H_ + nb);
            cpcommit();
        }
        // group 1: stage 1
        {
            char* dst = myA + ASTG;
            #pragma unroll
            for (int i = 0; i < 4; i++)
                cp16(dst + dstOff[i], hwarp + 64 + srcOff[i]);
            cpcommit();
        }

        for (int kt = 0; kt < NKT; kt++) {
            asm volatile("cp.async.wait_group 1;");
            if (kt + 2 < NKT) {
                char* dst = myA + ((kt + 2) % 3) * ASTG;
                const __half* hsrc = hwarp + (kt + 2) * 64;
                #pragma unroll
                for (int i = 0; i < 4; i++)
                    cp16(dst + dstOff[i], hsrc + srcOff[i]);
            }
            cpcommit();

            const uint32_t* A = (const uint32_t*)(myA + (kt % 3) * ASTG);
            #pragma unroll
            for (int c16 = 0; c16 < 4; c16++) {
                int co = c16 * 8;
                uint32_t a[4];
                a[0] = A[g * 36 + co + tg];
                a[1] = A[(g + 8) * 36 + co + tg];
                a[2] = A[g * 36 + co + tg + 4];
                a[3] = A[(g + 8) * 36 + co + tg + 4];
                int k16 = kh * 32 + kt * 4 + c16;
                #pragma unroll
                for (int gt = 0; gt < 3; gt++) {
                    uint2 bv = *(const uint2*)&Wp[((k16 * 3 + gt) * 32 + lane) * 2];
                    uint32_t b[2] = { bv.x, bv.y };
                    mma16(c[gt], a, b);
                }
            }
        }

        // drain all cp groups, then combine K-half partials through scratch
        asm volatile("cp.async.wait_group 0;");
        __syncthreads();
        if (kh == 1) {
            float4* s = (float4*)(scr + ((size_t)(wid - 8) * 32 + lane) * 12);
            s[0] = make_float4(c[0][0], c[0][1], c[0][2], c[0][3]);
            s[1] = make_float4(c[1][0], c[1][1], c[1][2], c[1][3]);
            s[2] = make_float4(c[2][0], c[2][1], c[2][2], c[2][3]);
        }
        __syncthreads();

        if (kh == 0) {
            const float4* s = (const float4*)(scr + ((size_t)wid * 32 + lane) * 12);
            float4 p0 = s[0], p1 = s[1], p2 = s[2];
            c[0][0] += p0.x; c[0][1] += p0.y; c[0][2] += p0.z; c[0][3] += p0.w;
            c[1][0] += p1.x; c[1][1] += p1.y; c[1][2] += p1.z; c[1][3] += p1.w;
            c[2][0] += p2.x; c[2][1] += p2.y; c[2][2] += p2.z; c[2][3] += p2.w;

            #pragma unroll
            for (int ep = 0; ep < 2; ep++) {
                int row = wM * 16 + g + ep * 8;
                const float* gxr = gxs + row * 28;
                float2 hv;
                #pragma unroll
                for (int hf = 0; hf < 2; hf++) {
                    int e = 2 * ep + hf;
                    int lc = 2 * tg + hf;
                    float xr = gxr[lc], xz = gxr[8 + lc], xn = gxr[16 + lc];
                    float hr = c[0][e] + bhs[lc];
                    float hz = c[1][e] + bhs[8 + lc];
                    float hn = c[2][e] + bhs[16 + lc];
                    float rr = sigm_ap(xr + hr);
                    float zz = sigm_ap(xz + hz);
                    float nn = tanh_ap(xn + rr * hn);
                    float ho = __half2float(hds[row * 8 + lc]);
                    float hnew = (1.f - zz) * nn + zz * ho;
                    (hf ? hv.y : hv.x) = hnew;
                }
                int col = nb + 2 * tg;
                __half2 hq = __floats2half2_rn(hv.x, hv.y);
                *(__half2*)&hout[(size_t)row * H_ + col] = hq;
                if (yout)
                    *(__half2*)&yout[(size_t)row * (T_ * H_) + (size_t)t * H_ + col] = hq;
                if (t == T_ - 1) *(float2*)&outf[(size_t)row * H_ + col] = hv;
            }
        }

        if (t != T_ - 1) flag_barrier(flags, bid, tid, (unsigned)(t + 1));
    }
}

// ---------------- launch ----------------
extern "C" void kernel_launch(void* const* d_in, const int* in_sizes, int n_in,
                              void* d_out, int out_size) {
    const int*   src  = (const int*)d_in[0];
    const float* emb  = (const float*)d_in[1];
    const float* wih0 = (const float*)d_in[2];
    const float* whh0 = (const float*)d_in[3];
    const float* bih0 = (const float*)d_in[4];
    const float* bhh0 = (const float*)d_in[5];
    const float* wih1 = (const float*)d_in[6];
    const float* whh1 = (const float*)d_in[7];
    const float* bih1 = (const float*)d_in[8];
    const float* bhh1 = (const float*)d_in[9];
    float* out = (float*)d_out;

    __half *x0, *y0, *pwih0, *pwih1, *h0, *h1;
    float *gx0, *gx1;
    unsigned *fl0, *fl1;
    cudaGetSymbolAddress((void**)&x0,    g_x0);
    cudaGetSymbolAddress((void**)&y0,    g_y0);
    cudaGetSymbolAddress((void**)&gx0,   g_gx0);
    cudaGetSymbolAddress((void**)&gx1,   g_gx1);
    cudaGetSymbolAddress((void**)&pwih0, g_wih0);
    cudaGetSymbolAddress((void**)&pwih1, g_wih1);
    cudaGetSymbolAddress((void**)&h0,    g_h0);
    cudaGetSymbolAddress((void**)&h1,    g_h1);
    cudaGetSymbolAddress((void**)&fl0,   g_flags0);
    cudaGetSymbolAddress((void**)&fl1,   g_flags1);

    cudaFuncSetAttribute(k_rec_persist, cudaFuncAttributeMaxDynamicSharedMemorySize, REC_SMEM);
    cudaFuncSetAttribute(k_gemm, cudaFuncAttributeMaxDynamicSharedMemorySize, GEMM_SMEM);

    // launch order keeps k_rec_persist at my-launch-index 3 for the ncu -s 5 window
    k_setup<<<2048, 256>>>(wih0, wih1);                                   // 0
    k_gather<<<NROW, 128>>>(src, emb, x0);                                // 1
    k_gemm<<<dim3(24, 512), 256, GEMM_SMEM>>>(x0, pwih0, bih0, gx0, E_);  // 2
    k_rec_persist<<<NCTA, THR, REC_SMEM>>>(whh0, gx0, bhh0, h0, y0, out, fl0);        // 3
    k_gemm<<<dim3(24, 512), 256, GEMM_SMEM>>>(y0, pwih1, bih1, gx1, H_);  // 4
    k_rec_persist<<<NCTA, THR, REC_SMEM>>>(whh1, gx1, bhh1, h1, nullptr, out + B_ * H_, fl1); // 5
}